// round 2
// baseline (speedup 1.0000x reference)
#include <cuda_runtime.h>
#include <cuda_fp16.h>
#include <cstdint>

#define N_C    16
#define DIN    1024
#define HID    128
#define TILE_M 128
#define KC     64

// ---------------- device scratch (module-load allocated, not runtime alloc) ----------------
__device__ __align__(1024) __half g_xh [67108864];        // 65536*1024 fp16 (128 MB)
__device__ __align__(1024) __half g_w1t[N_C * HID * DIN]; // [c][h][d] fp16 (K-major rows)
__device__ __align__(1024) __half g_w2t[N_C * HID * HID]; // [c][ho][hi] fp16 (K-major rows)

// ---------------- smem layout (dynamic) ----------------
#define OFF_SA0  0u
#define OFF_SA1  16384u
#define OFF_SB0  32768u
#define OFF_SB1  49152u
#define OFF_H1   65536u                 // two 16KB chunks: 65536, 81920
#define OFF_B1S  98304u
#define OFF_B2S  98816u
#define OFF_W3S  99328u
#define OFF_ACC  99840u
#define SMEM_TOTAL 100352u

#define SWZ(bo) ((bo) ^ (((bo) >> 3) & 0x70))

__device__ __forceinline__ uint32_t smem_u32(const void* p) {
    uint32_t a;
    asm("{ .reg .u64 t; cvta.to.shared.u64 t, %1; cvt.u32.u64 %0, t; }" : "=r"(a) : "l"(p));
    return a;
}

// cp.async a [128 x 128B] tile into swizzled smem; 256 threads, 16B each, 4 iters
__device__ __forceinline__ void cpa_tile(uint32_t soff_abs, const char* g,
                                         int stride_bytes, int tid) {
#pragma unroll
    for (int it = 0; it < 4; ++it) {
        int u = it * 256 + tid;
        int r = u >> 3, w = u & 7;
        uint32_t d = soff_abs + SWZ((uint32_t)(r * 128 + w * 16));
        const char* src = g + (size_t)r * stride_bytes + w * 16;
        asm volatile("cp.async.cg.shared.global [%0], [%1], 16;" :: "r"(d), "l"(src));
    }
}
#define CPA_COMMIT() asm volatile("cp.async.commit_group;" ::: "memory")
#define CPA_WAIT0()  asm volatile("cp.async.wait_group 0;" ::: "memory")
#define CPA_WAIT1()  asm volatile("cp.async.wait_group 1;" ::: "memory")

__device__ __forceinline__ void ldmA(uint32_t addr, uint32_t* f) {
    asm volatile("ldmatrix.sync.aligned.m8n8.x4.shared.b16 {%0,%1,%2,%3}, [%4];"
                 : "=r"(f[0]), "=r"(f[1]), "=r"(f[2]), "=r"(f[3]) : "r"(addr));
}
__device__ __forceinline__ void ldmB(uint32_t addr, uint32_t* f) {
    asm volatile("ldmatrix.sync.aligned.m8n8.x2.shared.b16 {%0,%1}, [%2];"
                 : "=r"(f[0]), "=r"(f[1]) : "r"(addr));
}
__device__ __forceinline__ void mma16816(float* c, const uint32_t* a, const uint32_t* b) {
    asm volatile(
        "mma.sync.aligned.m16n8k16.row.col.f32.f16.f16.f32 "
        "{%0,%1,%2,%3}, {%4,%5,%6,%7}, {%8,%9}, {%0,%1,%2,%3};"
        : "+f"(c[0]), "+f"(c[1]), "+f"(c[2]), "+f"(c[3])
        : "r"(a[0]), "r"(a[1]), "r"(a[2]), "r"(a[3]), "r"(b[0]), "r"(b[1]));
}

// one 64-wide K chunk: A tile [128 x 64] at sA, B tile [128 x 64] at sB (both swizzled)
__device__ __forceinline__ void gemm64(uint32_t sA, uint32_t sB,
                                       float acc[4][4][4], int lane, int wm, int wn) {
#pragma unroll
    for (int ks = 0; ks < 4; ++ks) {
        uint32_t a[4][4], b[4][2];
#pragma unroll
        for (int mt = 0; mt < 4; ++mt) {
            int row = wm * 64 + mt * 16 + (lane & 15);
            uint32_t bo = (uint32_t)(row * 128 + ks * 32 + ((lane >> 4) << 4));
            ldmA(sA + SWZ(bo), a[mt]);
        }
#pragma unroll
        for (int nt = 0; nt < 4; ++nt) {
            int row = wn * 32 + nt * 8 + (lane & 7);
            uint32_t bo = (uint32_t)(row * 128 + ks * 32 + (((lane >> 3) & 1) << 4));
            ldmB(sB + SWZ(bo), b[nt]);
        }
#pragma unroll
        for (int mt = 0; mt < 4; ++mt)
#pragma unroll
            for (int nt = 0; nt < 4; ++nt)
                mma16816(acc[mt][nt], a[mt], b[nt]);
    }
}

// ---------------- prep kernels ----------------
__global__ void prep_x_kernel(const float* __restrict__ x, int total4) {
    int i = blockIdx.x * blockDim.x + threadIdx.x;
    if (i < total4) {
        float4 v = ((const float4*)x)[i];
        __half2* o = (__half2*)g_xh;
        o[2 * i]     = __floats2half2_rn(v.x, v.y);
        o[2 * i + 1] = __floats2half2_rn(v.z, v.w);
    }
}

__global__ void prep_w_kernel(const float* __restrict__ W1, const float* __restrict__ W2) {
    int i = blockIdx.x * blockDim.x + threadIdx.x;
    const int n1 = N_C * DIN * HID;
    if (i < n1) {
        int c = i / (DIN * HID);
        int rem = i % (DIN * HID);
        int h = rem / DIN;
        int d = rem % DIN;
        g_w1t[i] = __float2half_rn(W1[(c * DIN + d) * HID + h]);
    } else {
        int k = i - n1;
        if (k < N_C * HID * HID) {
            int c = k / (HID * HID);
            int rem = k % (HID * HID);
            int ho = rem / HID;
            int hi = rem % HID;
            g_w2t[k] = __float2half_rn(W2[(c * HID + hi) * HID + ho]);
        }
    }
}

// ---------------- main fused MLP kernel ----------------
__global__ void __launch_bounds__(256, 2) mlp_main(
    const float* __restrict__ b1, const float* __restrict__ b2,
    const float* __restrict__ W3, const float* __restrict__ b3,
    float* __restrict__ out) {
    extern __shared__ char smem[];
    const uint32_t sbase = smem_u32(smem);
    const int tid  = threadIdx.x;
    const int lane = tid & 31;
    const int wid  = tid >> 5;
    const int wm   = wid >> 2;   // 0..1  (M warp)
    const int wn   = wid & 3;    // 0..3  (N warp)
    const int row0 = blockIdx.x * TILE_M;

    float* b1s    = (float*)(smem + OFF_B1S);
    float* b2s    = (float*)(smem + OFF_B2S);
    float* w3s    = (float*)(smem + OFF_W3S);
    float* rowacc = (float*)(smem + OFF_ACC);

    float acc[4][4][4];

#pragma unroll 1
    for (int c = 0; c < N_C; ++c) {
        // per-channel vectors into smem (first consumer is after many __syncthreads)
        if (tid < HID) {
            b1s[tid] = b1[c * HID + tid];
            b2s[tid] = b2[c * HID + tid];
            w3s[tid] = W3[c * HID + tid];
            rowacc[tid] = 0.f;
        }

        // ================= GEMM1: x[128,1024] @ W1t^T -> h1 =================
        const char* xg = (const char*)(g_xh + (size_t)row0 * DIN);
        const char* wg = (const char*)(g_w1t + (size_t)c * HID * DIN);

#pragma unroll
        for (int mt = 0; mt < 4; ++mt)
#pragma unroll
            for (int nt = 0; nt < 4; ++nt)
#pragma unroll
                for (int i = 0; i < 4; ++i) acc[mt][nt][i] = 0.f;

        cpa_tile(sbase + OFF_SA0, xg, DIN * 2, tid);
        cpa_tile(sbase + OFF_SB0, wg, DIN * 2, tid);
        CPA_COMMIT();

#pragma unroll 1
        for (int j = 0; j < DIN / KC; ++j) {
            if (j < DIN / KC - 1) {
                uint32_t sa = ((j + 1) & 1) ? OFF_SA1 : OFF_SA0;
                uint32_t sb = ((j + 1) & 1) ? OFF_SB1 : OFF_SB0;
                cpa_tile(sbase + sa, xg + (size_t)(j + 1) * KC * 2, DIN * 2, tid);
                cpa_tile(sbase + sb, wg + (size_t)(j + 1) * KC * 2, DIN * 2, tid);
                CPA_COMMIT();
                CPA_WAIT1();
            } else {
                CPA_WAIT0();
            }
            __syncthreads();
            gemm64(sbase + ((j & 1) ? OFF_SA1 : OFF_SA0),
                   sbase + ((j & 1) ? OFF_SB1 : OFF_SB0), acc, lane, wm, wn);
            __syncthreads();
        }

        // ============ epilogue 1: relu(acc + b1) -> fp16 smem (A of GEMM2) ============
#pragma unroll
        for (int mt = 0; mt < 4; ++mt) {
            int r1 = wm * 64 + mt * 16 + (lane >> 2);
#pragma unroll
            for (int nt = 0; nt < 4; ++nt) {
                int n = wn * 32 + nt * 8 + (lane & 3) * 2;
                uint32_t chb = OFF_H1 + (uint32_t)(n >> 6) * 16384u;
                uint32_t nc = (uint32_t)(n & 63);
                float* cc = acc[mt][nt];
                __half2 h0 = __floats2half2_rn(fmaxf(cc[0] + b1s[n], 0.f),
                                               fmaxf(cc[1] + b1s[n + 1], 0.f));
                __half2 h1 = __floats2half2_rn(fmaxf(cc[2] + b1s[n], 0.f),
                                               fmaxf(cc[3] + b1s[n + 1], 0.f));
                *(__half2*)(smem + chb + SWZ((uint32_t)r1 * 128u + nc * 2u)) = h0;
                *(__half2*)(smem + chb + SWZ((uint32_t)(r1 + 8) * 128u + nc * 2u)) = h1;
            }
        }
        __syncthreads();

        // ================= GEMM2: h1[128,128] @ W2t^T =================
        const char* w2g = (const char*)(g_w2t + (size_t)c * HID * HID);
        cpa_tile(sbase + OFF_SB0, w2g, HID * 2, tid);
        cpa_tile(sbase + OFF_SB1, w2g + (size_t)KC * 2, HID * 2, tid);
        CPA_COMMIT();

#pragma unroll
        for (int mt = 0; mt < 4; ++mt)
#pragma unroll
            for (int nt = 0; nt < 4; ++nt)
#pragma unroll
                for (int i = 0; i < 4; ++i) acc[mt][nt][i] = 0.f;

        CPA_WAIT0();
        __syncthreads();
        gemm64(sbase + OFF_H1,          sbase + OFF_SB0, acc, lane, wm, wn);
        gemm64(sbase + OFF_H1 + 16384u, sbase + OFF_SB1, acc, lane, wm, wn);

        // ============ epilogue 2: out = relu(acc + b2) . W3 + b3 ============
#pragma unroll
        for (int mt = 0; mt < 4; ++mt) {
            float p1 = 0.f, p2 = 0.f;
#pragma unroll
            for (int nt = 0; nt < 4; ++nt) {
                int n = wn * 32 + nt * 8 + (lane & 3) * 2;
                float* cc = acc[mt][nt];
                p1 += fmaxf(cc[0] + b2s[n], 0.f) * w3s[n]
                    + fmaxf(cc[1] + b2s[n + 1], 0.f) * w3s[n + 1];
                p2 += fmaxf(cc[2] + b2s[n], 0.f) * w3s[n]
                    + fmaxf(cc[3] + b2s[n + 1], 0.f) * w3s[n + 1];
            }
            p1 += __shfl_xor_sync(0xFFFFFFFFu, p1, 1);
            p1 += __shfl_xor_sync(0xFFFFFFFFu, p1, 2);
            p2 += __shfl_xor_sync(0xFFFFFFFFu, p2, 1);
            p2 += __shfl_xor_sync(0xFFFFFFFFu, p2, 2);
            if ((lane & 3) == 0) {
                int r = wm * 64 + mt * 16 + (lane >> 2);
                atomicAdd(&rowacc[r], p1);
                atomicAdd(&rowacc[r + 8], p2);
            }
        }
        __syncthreads();
        if (tid < TILE_M)
            out[(size_t)(row0 + tid) * N_C + c] = rowacc[tid] + b3[c];
        __syncthreads();  // protect smem vectors before next channel rewrites them
    }
}

// ---------------- launch ----------------
extern "C" void kernel_launch(void* const* d_in, const int* in_sizes, int n_in,
                              void* d_out, int out_size) {
    const float* x  = (const float*)d_in[0];
    const float* W1 = (const float*)d_in[1];
    const float* b1 = (const float*)d_in[2];
    const float* W2 = (const float*)d_in[3];
    const float* b2 = (const float*)d_in[4];
    const float* W3 = (const float*)d_in[5];
    const float* b3 = (const float*)d_in[6];
    float* out = (float*)d_out;

    const int npts = in_sizes[0] / DIN;        // 65536
    const int total4 = npts * (DIN / 4);

    prep_x_kernel<<<(total4 + 255) / 256, 256>>>(x, total4);
    const int wtot = N_C * DIN * HID + N_C * HID * HID;
    prep_w_kernel<<<(wtot + 255) / 256, 256>>>(W1, W2);

    cudaFuncSetAttribute(mlp_main, cudaFuncAttributeMaxDynamicSharedMemorySize, SMEM_TOTAL);
    mlp_main<<<npts / TILE_M, 256, SMEM_TOTAL>>>(b1, b2, W3, b3, out);
}